// round 1
// baseline (speedup 1.0000x reference)
#include <cuda_runtime.h>
#include <cuda_bf16.h>

// Problem constants (fixed by reference setup_inputs)
#define BATCH   16
#define NHEAD   16
#define HDIM    64
#define HW      4096                 // H*W = 64*64
#define NROWS   (BATCH * NHEAD * HDIM)   // 16384 rows of 4096 floats
#define LSEQ    16                   // sequence length for the tiny MHA (= nH)
#define BN      4                    // bottleneck dim
#define MHA_H   2                    // heads
#define DH      2                    // head dim = BN / MHA_H

// Scratch (no allocations allowed in kernel_launch)
__device__ float g_pooled[NROWS];   // [B, nH, hd] row-major (= per-row mean of x)
__device__ float g_delta [NROWS];   // [B, nH, hd]

// ---------------------------------------------------------------------------
// Pass 1: per-row mean over H*W. One block per row, 256 threads, float4 loads.
// ---------------------------------------------------------------------------
__global__ __launch_bounds__(256) void pool_kernel(const float* __restrict__ x) {
    const int row = blockIdx.x;
    const float4* __restrict__ xr =
        reinterpret_cast<const float4*>(x) + (size_t)row * (HW / 4);

    float s = 0.f;
#pragma unroll
    for (int i = 0; i < 4; i++) {
        float4 v = xr[threadIdx.x + i * 256];
        s += (v.x + v.y) + (v.z + v.w);
    }
    // warp reduce
#pragma unroll
    for (int off = 16; off; off >>= 1)
        s += __shfl_xor_sync(0xffffffffu, s, off);

    __shared__ float ws[8];
    if ((threadIdx.x & 31) == 0) ws[threadIdx.x >> 5] = s;
    __syncthreads();
    if (threadIdx.x < 8) {
        float v = ws[threadIdx.x];
#pragma unroll
        for (int off = 4; off; off >>= 1)
            v += __shfl_xor_sync(0x000000ffu, v, off);
        if (threadIdx.x == 0)
            g_pooled[row] = v * (1.0f / (float)HW);
    }
}

// ---------------------------------------------------------------------------
// Pass 2: compress -> MHA(2 heads over bn=4) -> out_proj -> expand -> LN.
// One block per batch element, 64 threads. Everything fits in smem/registers.
// ---------------------------------------------------------------------------
__global__ __launch_bounds__(64) void middle_kernel(
    const float* __restrict__ cw,  const float* __restrict__ cb,
    const float* __restrict__ ipw, const float* __restrict__ ipb,
    const float* __restrict__ opw, const float* __restrict__ opb,
    const float* __restrict__ ew,  const float* __restrict__ eb,
    const float* __restrict__ lnw, const float* __restrict__ lnb,
    const float* __restrict__ gate)
{
    const int b = blockIdx.x;
    const int t = threadIdx.x;

    __shared__ float pooled[LSEQ][HDIM];   // residual / input
    __shared__ float xc    [LSEQ][BN];
    __shared__ float qkv   [LSEQ][3 * BN];
    __shared__ float ov    [LSEQ][BN];     // attention output (pre out_proj)
    __shared__ float xattn [LSEQ][BN];
    __shared__ float wred  [2];

    // load pooled[b] : 16 x 64
    const float* __restrict__ pb = g_pooled + (size_t)b * LSEQ * HDIM;
#pragma unroll
    for (int i = t; i < LSEQ * HDIM; i += 64)
        pooled[i / HDIM][i % HDIM] = pb[i];
    __syncthreads();

    // compress: xc[l][e] = pooled[l] . cw[e] + cb[e]   (64 outputs, 1/thread)
    {
        const int l = t / BN, e = t % BN;
        float s = cb[e];
#pragma unroll
        for (int k = 0; k < HDIM; k++)
            s = fmaf(pooled[l][k], cw[e * HDIM + k], s);
        xc[l][e] = s;
    }
    __syncthreads();

    // qkv: [16, 12]
    for (int idx = t; idx < LSEQ * 3 * BN; idx += 64) {
        const int l = idx / (3 * BN), e = idx % (3 * BN);
        float s = ipb[e];
#pragma unroll
        for (int k = 0; k < BN; k++)
            s = fmaf(xc[l][k], ipw[e * BN + k], s);
        qkv[l][e] = s;
    }
    __syncthreads();

    // attention: 2 heads, dh=2, L=16. One (h, q) pair per thread (32 active).
    if (t < MHA_H * LSEQ) {
        const int h = t / LSEQ, q = t % LSEQ;
        const float scale = rsqrtf((float)DH);
        const float q0 = qkv[q][h * DH + 0];
        const float q1 = qkv[q][h * DH + 1];

        float sc[LSEQ];
        float m = -1e30f;
#pragma unroll
        for (int k = 0; k < LSEQ; k++) {
            float s = (q0 * qkv[k][BN + h * DH + 0] +
                       q1 * qkv[k][BN + h * DH + 1]) * scale;
            sc[k] = s;
            m = fmaxf(m, s);
        }
        float den = 0.f;
#pragma unroll
        for (int k = 0; k < LSEQ; k++) {
            sc[k] = __expf(sc[k] - m);
            den += sc[k];
        }
        const float inv = 1.0f / den;
        float o0 = 0.f, o1 = 0.f;
#pragma unroll
        for (int k = 0; k < LSEQ; k++) {
            const float a = sc[k] * inv;
            o0 = fmaf(a, qkv[k][2 * BN + h * DH + 0], o0);
            o1 = fmaf(a, qkv[k][2 * BN + h * DH + 1], o1);
        }
        ov[q][h * DH + 0] = o0;
        ov[q][h * DH + 1] = o1;
    }
    __syncthreads();

    // out_proj: 64 outputs
    {
        const int l = t / BN, e = t % BN;
        float s = opb[e];
#pragma unroll
        for (int k = 0; k < BN; k++)
            s = fmaf(ov[l][k], opw[e * BN + k], s);
        xattn[l][e] = s;
    }
    __syncthreads();

    // expand + residual + gate + layernorm + delta. Thread t = hd index.
    const float g = gate[0];
    const float lw = lnw[t];
    const float lb = lnb[t];
    float* __restrict__ dout = g_delta + (size_t)b * LSEQ * HDIM;

    for (int l = 0; l < LSEQ; l++) {
        float xe = eb[t];
#pragma unroll
        for (int k = 0; k < BN; k++)
            xe = fmaf(xattn[l][k], ew[t * BN + k], xe);
        const float res = pooled[l][t];
        const float y = fmaf(g, xe, res);

        // mean over 64 lanes (2 warps)
        float s = y;
#pragma unroll
        for (int off = 16; off; off >>= 1)
            s += __shfl_xor_sync(0xffffffffu, s, off);
        if ((t & 31) == 0) wred[t >> 5] = s;
        __syncthreads();
        const float mu = (wred[0] + wred[1]) * (1.0f / (float)HDIM);
        __syncthreads();

        const float dy = y - mu;
        float s2 = dy * dy;
#pragma unroll
        for (int off = 16; off; off >>= 1)
            s2 += __shfl_xor_sync(0xffffffffu, s2, off);
        if ((t & 31) == 0) wred[t >> 5] = s2;
        __syncthreads();
        const float var = (wred[0] + wred[1]) * (1.0f / (float)HDIM);

        const float ln = dy * rsqrtf(var + 1e-5f) * lw + lb;
        dout[l * HDIM + t] = ln - res;
        __syncthreads();
    }
}

// ---------------------------------------------------------------------------
// Pass 3: out = x + delta[row], broadcast over the 4096 elements of each row.
// Reverse row order so the first reads hit the x-tail still resident in L2
// from pass 1.
// ---------------------------------------------------------------------------
__global__ __launch_bounds__(256) void add_kernel(const float* __restrict__ x,
                                                  float* __restrict__ out) {
    const int row = (NROWS - 1) - blockIdx.x;
    const float d = g_delta[row];
    const float4* __restrict__ xr =
        reinterpret_cast<const float4*>(x) + (size_t)row * (HW / 4);
    float4* __restrict__ orow =
        reinterpret_cast<float4*>(out) + (size_t)row * (HW / 4);

#pragma unroll
    for (int i = 0; i < 4; i++) {
        const int idx = threadIdx.x + i * 256;
        float4 v = xr[idx];
        v.x += d; v.y += d; v.z += d; v.w += d;
        orow[idx] = v;
    }
}

// ---------------------------------------------------------------------------
extern "C" void kernel_launch(void* const* d_in, const int* in_sizes, int n_in,
                              void* d_out, int out_size) {
    const float* x   = (const float*)d_in[0];
    const float* cw  = (const float*)d_in[1];
    const float* cb  = (const float*)d_in[2];
    const float* ipw = (const float*)d_in[3];
    const float* ipb = (const float*)d_in[4];
    const float* opw = (const float*)d_in[5];
    const float* opb = (const float*)d_in[6];
    const float* ew  = (const float*)d_in[7];
    const float* eb  = (const float*)d_in[8];
    const float* lnw = (const float*)d_in[9];
    const float* lnb = (const float*)d_in[10];
    const float* gt  = (const float*)d_in[11];
    float* out = (float*)d_out;

    pool_kernel<<<NROWS, 256>>>(x);
    middle_kernel<<<BATCH, 64>>>(cw, cb, ipw, ipb, opw, opb, ew, eb, lnw, lnb, gt);
    add_kernel<<<NROWS, 256>>>(x, out);
}